// round 8
// baseline (speedup 1.0000x reference)
#include <cuda_runtime.h>
#include <math.h>
#include <stdint.h>

#define B_  4
#define S_  2048
#define H_  1024
#define NH_ 16
#define HD_ 64
#define M_  (B_ * S_)
#define SCALE_INV 0.125f

// Scratch (device globals — no allocation allowed)
__device__ float g_Q[M_ * H_];            // [B,NH,S,HD]  tf32-rounded, pre-scaled by 1/8
__device__ float g_K[M_ * H_];            // [B,NH,S,HD]  tf32-rounded
__device__ float g_V[M_ * H_];            // [B,NH,S,HD]  tf32-rounded
__device__ float g_X[M_ * H_];            // [B,S,H]      tf32-rounded
__device__ float g_psum[64 * S_ * 32];    // [bh][q][kblock(64)] partial row sums
__device__ float g_rIn[3][M_ * H_];       // tf32-rounded query/key/value
__device__ float g_rW[4][H_ * H_];        // tf32-rounded Wq,Wk,Wv,Wo

// ---------------------------------------------------------------------------
__device__ __forceinline__ uint32_t f2tf32(float x) {  // round-to-nearest tf32
    uint32_t r; asm("cvt.rna.tf32.f32 %0, %1;" : "=r"(r) : "f"(x)); return r;
}
__device__ __forceinline__ float tf32f(float x) { return __uint_as_float(f2tf32(x)); }

__device__ __forceinline__ void mma_tf32(float* c, const uint32_t* a, const uint32_t* b) {
    asm volatile("mma.sync.aligned.m16n8k8.row.col.f32.tf32.tf32.f32 "
        "{%0,%1,%2,%3}, {%4,%5,%6,%7}, {%8,%9}, {%0,%1,%2,%3};"
        : "+f"(c[0]), "+f"(c[1]), "+f"(c[2]), "+f"(c[3])
        : "r"(a[0]), "r"(a[1]), "r"(a[2]), "r"(a[3]), "r"(b[0]), "r"(b[1]));
}

__device__ __forceinline__ void lda_frag(uint32_t* a, const float* s, int lds,
                                         int mbase, int k, int lane) {
    const float* p = s + (size_t)(mbase + (lane >> 2)) * lds + k + (lane & 3);
    a[0] = __float_as_uint(p[0]);
    a[1] = __float_as_uint(p[8 * lds]);
    a[2] = __float_as_uint(p[4]);
    a[3] = __float_as_uint(p[8 * lds + 4]);
}
__device__ __forceinline__ void ldb_frag(uint32_t* b, const float* s, int lds,
                                         int nbase, int k, int lane) {
    const float* p = s + (size_t)(nbase + (lane >> 2)) * lds + k + (lane & 3);
    b[0] = __float_as_uint(p[0]);
    b[1] = __float_as_uint(p[4]);
}

__device__ __forceinline__ uint32_t smaddr(const void* p) {
    return (uint32_t)__cvta_generic_to_shared(p);
}
#define CP_ASYNC16(dst, src) \
    asm volatile("cp.async.cg.shared.global [%0], [%1], 16;" :: "r"(dst), "l"(src))
#define CP_COMMIT() asm volatile("cp.async.commit_group;" ::: "memory")
#define CP_WAIT0()  asm volatile("cp.async.wait_group 0;" ::: "memory")
#define CP_WAIT1()  asm volatile("cp.async.wait_group 1;" ::: "memory")

// ---------------------------------------------------------------------------
// Streaming tf32 pre-round: out[i] = tf32(in[i]).
// ---------------------------------------------------------------------------
__global__ __launch_bounds__(256) void round_tf32(const float* __restrict__ in,
                                                  float* __restrict__ out, int n4) {
    int i = blockIdx.x * 256 + threadIdx.x;
    if (i < n4) {
        float4 v = ((const float4*)in)[i];
        v.x = tf32f(v.x); v.y = tf32f(v.y); v.z = tf32f(v.z); v.w = tf32f(v.w);
        ((float4*)out)[i] = v;
    }
}

// ---------------------------------------------------------------------------
// Projection GEMM on PRE-ROUNDED operands (zero cvt in mainloop).
// C[m,n] = A[m,:]·W[n,:] + bias[n]. Tile 128x128, 2-stage cp.async.
// mode 0: out[m][n] fp32; mode 1: out[b,h,s,d] tf32; mode 2: tf32 * 1/8 (Q)
// ---------------------------------------------------------------------------
__global__ __launch_bounds__(256, 2) void proj_mma(const float* __restrict__ A,
                                                   const float* __restrict__ W,
                                                   const float* __restrict__ bias,
                                                   float* __restrict__ out, int mode) {
    __shared__ float sA[2][128][36];
    __shared__ float sB[2][128][36];
    const int tid = threadIdx.x, lane = tid & 31, w = tid >> 5;
    const int wm = (w >> 2) * 64, wn = (w & 3) * 32;
    const int m0 = blockIdx.y * 128, n0 = blockIdx.x * 128;

    float acc[4][4][4] = {};

    #pragma unroll
    for (int i = tid; i < 1024; i += 256) {
        int r = i >> 3, c4 = (i & 7) * 4;
        CP_ASYNC16(smaddr(&sA[0][r][c4]), &A[(size_t)(m0 + r) * H_ + c4]);
        CP_ASYNC16(smaddr(&sB[0][r][c4]), &W[(size_t)(n0 + r) * H_ + c4]);
    }
    CP_COMMIT();

    for (int it = 0; it < 32; it++) {
        const int s = it & 1;
        if (it + 1 < 32) {
            const int kn = (it + 1) * 32, sn = s ^ 1;
            #pragma unroll
            for (int i = tid; i < 1024; i += 256) {
                int r = i >> 3, c4 = (i & 7) * 4;
                CP_ASYNC16(smaddr(&sA[sn][r][c4]), &A[(size_t)(m0 + r) * H_ + kn + c4]);
                CP_ASYNC16(smaddr(&sB[sn][r][c4]), &W[(size_t)(n0 + r) * H_ + kn + c4]);
            }
            CP_COMMIT();
            CP_WAIT1();
        } else {
            CP_WAIT0();
        }
        __syncthreads();

        #pragma unroll
        for (int ks = 0; ks < 4; ks++) {
            uint32_t af[4][4], bf[4][2];
            #pragma unroll
            for (int mt = 0; mt < 4; mt++) lda_frag(af[mt], &sA[s][0][0], 36, wm + mt * 16, ks * 8, lane);
            #pragma unroll
            for (int nt = 0; nt < 4; nt++) ldb_frag(bf[nt], &sB[s][0][0], 36, wn + nt * 8, ks * 8, lane);
            #pragma unroll
            for (int mt = 0; mt < 4; mt++)
                #pragma unroll
                for (int nt = 0; nt < 4; nt++)
                    mma_tf32(acc[mt][nt], af[mt], bf[nt]);
        }
        __syncthreads();
    }

    #pragma unroll
    for (int mt = 0; mt < 4; mt++) {
        #pragma unroll
        for (int nt = 0; nt < 4; nt++) {
            int r0 = m0 + wm + mt * 16 + (lane >> 2);
            int c0 = n0 + wn + nt * 8 + (lane & 3) * 2;
            #pragma unroll
            for (int e = 0; e < 4; e++) {
                int m = r0 + (e >> 1) * 8;
                int n = c0 + (e & 1);
                float v = acc[mt][nt][e] + bias[n];
                if (mode == 0) {
                    out[(size_t)m * H_ + n] = v;
                } else {
                    int b = m >> 11, sq = m & 2047, h = n >> 6, dd = n & 63;
                    float o = tf32f(v);
                    if (mode == 2) o *= SCALE_INV;   // exact (exponent shift)
                    out[(((size_t)(b * NH_ + h) * S_) + sq) * HD_ + dd] = o;
                }
            }
        }
    }
}

// ---------------------------------------------------------------------------
// Energy + exp + mask, head-reuse version. One CTA handles a (q0,k0) tile for
// ALL 16 heads of one batch: the mask bit-pack is computed once and reused.
// Q pre-scaled by 1/8. Writes tf32-rounded unnormalized P + psum.
// ---------------------------------------------------------------------------
__global__ __launch_bounds__(256, 3) void energy_exp(const int* __restrict__ mask,
                                                     float* __restrict__ attn,
                                                     float* __restrict__ psum) {
    __shared__ union {
        struct { float A[128][68]; float B[64][68]; } ld;
        float E[128][68];
    } sm;
    const int tid = threadIdx.x, lane = tid & 31, w = tid >> 5;
    const int wm = (w >> 1) * 32, wn = (w & 1) * 32;
    const int b = blockIdx.z;
    const int q0 = blockIdx.y * 128, k0 = blockIdx.x * 64;
    const int kblk = blockIdx.x;
    const int cl = (tid & 15) * 4;
    const int k = k0 + cl;

    uint32_t pmask = 0;

    for (int h = 0; h < 16; h++) {
        const int bh = b * 16 + h;
        const float* Qb = g_Q + (size_t)bh * S_ * HD_;
        const float* Kb = g_K + (size_t)bh * S_ * HD_;

        // Tile loads for this head: Q[128][64], K[64][64]
        #pragma unroll
        for (int i = tid; i < 2048; i += 256) {
            int r = i >> 4, c4 = (i & 15) * 4;
            CP_ASYNC16(smaddr(&sm.ld.A[r][c4]), &Qb[(size_t)(q0 + r) * HD_ + c4]);
        }
        #pragma unroll
        for (int i = tid; i < 1024; i += 256) {
            int r = i >> 4, c4 = (i & 15) * 4;
            CP_ASYNC16(smaddr(&sm.ld.B[r][c4]), &Kb[(size_t)(k0 + r) * HD_ + c4]);
        }
        CP_COMMIT();

        if (h == 0) {
            // Mask prefetch + bit-pack ONCE (shared by all 16 heads).
            const int* mb = mask + (size_t)b * S_ * S_;
            #pragma unroll
            for (int j = 0; j < 8; j++) {
                int q = q0 + j * 16 + (tid >> 4);
                int4 mv = *(const int4*)&mb[(size_t)q * S_ + k];
                uint32_t bits = (mv.x ? 1u : 0u) | (mv.y ? 2u : 0u)
                              | (mv.z ? 4u : 0u) | (mv.w ? 8u : 0u);
                pmask |= bits << (4 * j);
            }
        }

        CP_WAIT0();
        __syncthreads();

        float acc[2][4][4] = {};
        #pragma unroll
        for (int ks = 0; ks < 8; ks++) {
            uint32_t af[2][4], bf[4][2];
            #pragma unroll
            for (int mt = 0; mt < 2; mt++) lda_frag(af[mt], &sm.ld.A[0][0], 68, wm + mt * 16, ks * 8, lane);
            #pragma unroll
            for (int nt = 0; nt < 4; nt++) ldb_frag(bf[nt], &sm.ld.B[0][0], 68, wn + nt * 8, ks * 8, lane);
            #pragma unroll
            for (int mt = 0; mt < 2; mt++)
                #pragma unroll
                for (int nt = 0; nt < 4; nt++)
                    mma_tf32(acc[mt][nt], af[mt], bf[nt]);
        }
        __syncthreads();   // Q/K reads done before E overwrites

        // Stage E (128x64) into smem.
        #pragma unroll
        for (int mt = 0; mt < 2; mt++) {
            int r = wm + mt * 16 + (lane >> 2);
            #pragma unroll
            for (int nt = 0; nt < 4; nt++) {
                int lc = wn + nt * 8 + (lane & 3) * 2;
                sm.E[r][lc]         = acc[mt][nt][0];
                sm.E[r][lc + 1]     = acc[mt][nt][1];
                sm.E[r + 8][lc]     = acc[mt][nt][2];
                sm.E[r + 8][lc + 1] = acc[mt][nt][3];
            }
        }
        __syncthreads();

        // Coalesced epilogue (no global loads; mask in pmask).
        float* ab = attn + (size_t)bh * S_ * S_;
        #pragma unroll
        for (int j = 0; j < 8; j++) {
            int row = j * 16 + (tid >> 4);
            int q = q0 + row;
            float4 ev = *(float4*)&sm.E[row][cl];
            uint32_t bits = (pmask >> (4 * j)) & 0xfu;
            float p0 = (bits & 1u) ? tf32f(__expf(ev.x)) : 0.f;
            float p1 = (bits & 2u) ? tf32f(__expf(ev.y)) : 0.f;
            float p2 = (bits & 4u) ? tf32f(__expf(ev.z)) : 0.f;
            float p3 = (bits & 8u) ? tf32f(__expf(ev.w)) : 0.f;
            float4 pv4 = { p0, p1, p2, p3 };
            *(float4*)&ab[(size_t)q * S_ + k] = pv4;
            float v = (p0 + p1) + (p2 + p3);
            v += __shfl_xor_sync(0xffffffffu, v, 1);
            v += __shfl_xor_sync(0xffffffffu, v, 2);
            v += __shfl_xor_sync(0xffffffffu, v, 4);
            v += __shfl_xor_sync(0xffffffffu, v, 8);
            if ((tid & 15) == 0)
                psum[((size_t)bh * S_ + q) * 32 + kblk] = v;
        }
        __syncthreads();   // epilogue E-reads done before next head's loads
    }
}

// ---------------------------------------------------------------------------
// PV + normalize. Tile 128(q) x 64(d), K chunked by 32, 2-stage cp.async.
// MMA on unnormalized tf32 P; normalization at stores. X stored tf32-rounded.
// ---------------------------------------------------------------------------
__global__ __launch_bounds__(256, 3) void pv_norm(float* __restrict__ attn,
                                                  const float* __restrict__ psum) {
    __shared__ float sP[2][128][36];
    __shared__ float sV[2][32][68];
    __shared__ float sInv[128];
    const int tid = threadIdx.x, lane = tid & 31, w = tid >> 5;
    const int wm = (w >> 1) * 32, wn = (w & 1) * 32;
    const int bh = blockIdx.y, b = bh >> 4, h = bh & 15;
    const int q0 = blockIdx.x * 128;
    float* Pb = attn + (size_t)bh * S_ * S_;
    const float* Vb = g_V + (size_t)bh * S_ * HD_;

    if (tid < 128) {
        const float* ps = psum + ((size_t)bh * S_ + q0 + tid) * 32;
        float sum = 0.f;
        #pragma unroll
        for (int i = 0; i < 32; i++) sum += ps[i];
        sInv[tid] = 1.0f / sum;
    }

    #pragma unroll
    for (int i = tid; i < 1024; i += 256) {
        int r = i >> 3, c4 = (i & 7) * 4;
        CP_ASYNC16(smaddr(&sP[0][r][c4]), &Pb[(size_t)(q0 + r) * S_ + c4]);
    }
    #pragma unroll
    for (int i = tid; i < 512; i += 256) {
        int r = i >> 4, c4 = (i & 15) * 4;
        CP_ASYNC16(smaddr(&sV[0][r][c4]), &Vb[(size_t)r * HD_ + c4]);
    }
    CP_COMMIT();

    float acc[2][4][4] = {};

    for (int it = 0; it < 64; it++) {
        const int kc = it * 32, s = it & 1;
        if (it + 1 < 64) {
            const int kn = kc + 32, sn = s ^ 1;
            #pragma unroll
            for (int i = tid; i < 1024; i += 256) {
                int r = i >> 3, c4 = (i & 7) * 4;
                CP_ASYNC16(smaddr(&sP[sn][r][c4]), &Pb[(size_t)(q0 + r) * S_ + kn + c4]);
            }
            #pragma unroll
            for (int i = tid; i < 512; i += 256) {
                int r = i >> 4, c4 = (i & 15) * 4;
                CP_ASYNC16(smaddr(&sV[sn][r][c4]), &Vb[(size_t)(kn + r) * HD_ + c4]);
            }
            CP_COMMIT();
            CP_WAIT1();
        } else {
            CP_WAIT0();
        }
        __syncthreads();

        #pragma unroll
        for (int ks = 0; ks < 4; ks++) {
            uint32_t af[2][4], bf[4][2];
            #pragma unroll
            for (int mt = 0; mt < 2; mt++) lda_frag(af[mt], &sP[s][0][0], 36, wm + mt * 16, ks * 8, lane);
            #pragma unroll
            for (int nt = 0; nt < 4; nt++) {
                const float* p = &sV[s][ks * 8 + (lane & 3)][wn + nt * 8 + (lane >> 2)];
                bf[nt][0] = __float_as_uint(p[0]);
                bf[nt][1] = __float_as_uint(p[4 * 68]);
            }
            #pragma unroll
            for (int mt = 0; mt < 2; mt++)
                #pragma unroll
                for (int nt = 0; nt < 4; nt++)
                    mma_tf32(acc[mt][nt], af[mt], bf[nt]);
        }

        #pragma unroll
        for (int i = tid; i < 1024; i += 256) {
            int r = i >> 3, c4 = (i & 7) * 4;
            float inv = sInv[r];
            float4 v = *(float4*)&sP[s][r][c4];
            v.x *= inv; v.y *= inv; v.z *= inv; v.w *= inv;
            *(float4*)&Pb[(size_t)(q0 + r) * S_ + kc + c4] = v;
        }
        __syncthreads();
    }

    #pragma unroll
    for (int mt = 0; mt < 2; mt++) {
        #pragma unroll
        for (int nt = 0; nt < 4; nt++) {
            int rr = wm + mt * 16 + (lane >> 2);
            int c0 = wn + nt * 8 + (lane & 3) * 2;
            #pragma unroll
            for (int e = 0; e < 4; e++) {
                int rl = rr + (e >> 1) * 8;
                int q = q0 + rl;
                int d = c0 + (e & 1);
                g_X[((size_t)(b * S_ + q)) * H_ + h * HD_ + d] = tf32f(acc[mt][nt][e] * sInv[rl]);
            }
        }
    }
}

// ---------------------------------------------------------------------------
extern "C" void kernel_launch(void* const* d_in, const int* in_sizes, int n_in,
                              void* d_out, int out_size) {
    const float* query = (const float*)d_in[0];
    const float* key   = (const float*)d_in[1];
    const float* value = (const float*)d_in[2];
    const int*   mask  = (const int*)d_in[3];
    const float* Wq = (const float*)d_in[4];  const float* bq = (const float*)d_in[5];
    const float* Wk = (const float*)d_in[6];  const float* bk = (const float*)d_in[7];
    const float* Wv = (const float*)d_in[8];  const float* bv = (const float*)d_in[9];
    const float* Wo = (const float*)d_in[10]; const float* bo = (const float*)d_in[11];

    float* out  = (float*)d_out;
    float* attn = out + (size_t)B_ * S_ * H_;

    float *gQ, *gK, *gV, *gX, *gPS, *gIn, *gW;
    cudaGetSymbolAddress((void**)&gQ, g_Q);
    cudaGetSymbolAddress((void**)&gK, g_K);
    cudaGetSymbolAddress((void**)&gV, g_V);
    cudaGetSymbolAddress((void**)&gX, g_X);
    cudaGetSymbolAddress((void**)&gPS, g_psum);
    cudaGetSymbolAddress((void**)&gIn, g_rIn);
    cudaGetSymbolAddress((void**)&gW, g_rW);

    float* rq = gIn;                 // rounded query
    float* rk = gIn + (size_t)M_ * H_;
    float* rv = gIn + (size_t)2 * M_ * H_;
    float* rWq = gW;
    float* rWk = gW + (size_t)H_ * H_;
    float* rWv = gW + (size_t)2 * H_ * H_;
    float* rWo = gW + (size_t)3 * H_ * H_;

    const int nIn4 = M_ * H_ / 4;    // 2M float4
    const int nW4  = H_ * H_ / 4;    // 256K float4
    round_tf32<<<(nIn4 + 255) / 256, 256>>>(query, rq, nIn4);
    round_tf32<<<(nIn4 + 255) / 256, 256>>>(key,   rk, nIn4);
    round_tf32<<<(nIn4 + 255) / 256, 256>>>(value, rv, nIn4);
    round_tf32<<<(nW4 + 255) / 256, 256>>>(Wq, rWq, nW4);
    round_tf32<<<(nW4 + 255) / 256, 256>>>(Wk, rWk, nW4);
    round_tf32<<<(nW4 + 255) / 256, 256>>>(Wv, rWv, nW4);
    round_tf32<<<(nW4 + 255) / 256, 256>>>(Wo, rWo, nW4);

    dim3 grid_proj(H_ / 128, M_ / 128);        // (8, 64)
    proj_mma<<<grid_proj, 256>>>(rq, rWq, bq, gQ, 2);   // Q pre-scaled 1/8
    proj_mma<<<grid_proj, 256>>>(rk, rWk, bk, gK, 1);
    proj_mma<<<grid_proj, 256>>>(rv, rWv, bv, gV, 1);

    dim3 grid_e(S_ / 64, S_ / 128, B_);        // (32, 16, 4), 16 heads looped
    energy_exp<<<grid_e, 256>>>(mask, attn, gPS);

    dim3 grid_pv(S_ / 128, B_ * NH_);          // (16, 64)
    pv_norm<<<grid_pv, 256>>>(attn, gPS);

    proj_mma<<<grid_proj, 256>>>(gX, rWo, bo, out, 0);
}

// round 10
// speedup vs baseline: 1.0088x; 1.0088x over previous
#include <cuda_runtime.h>
#include <math.h>
#include <stdint.h>

#define B_  4
#define S_  2048
#define H_  1024
#define NH_ 16
#define HD_ 64
#define M_  (B_ * S_)
#define SCALE_INV 0.125f

// Scratch (device globals — no allocation allowed)
__device__ float g_Q[M_ * H_];            // [B,NH,S,HD]  tf32-rounded, pre-scaled by 1/8
__device__ float g_K[M_ * H_];            // [B,NH,S,HD]  tf32-rounded
__device__ float g_V[M_ * H_];            // [B,NH,S,HD]  tf32-rounded
__device__ float g_X[M_ * H_];            // [B,S,H]      tf32-rounded
__device__ float g_psum[64 * S_ * 32];    // [bh][q][kblock(64)] partial row sums
__device__ float g_rW[4][H_ * H_];        // tf32-rounded Wq,Wk,Wv,Wo

// ---------------------------------------------------------------------------
__device__ __forceinline__ uint32_t f2tf32(float x) {  // round-to-nearest tf32
    uint32_t r; asm("cvt.rna.tf32.f32 %0, %1;" : "=r"(r) : "f"(x)); return r;
}
__device__ __forceinline__ float tf32f(float x) { return __uint_as_float(f2tf32(x)); }

__device__ __forceinline__ void mma_tf32(float* c, const uint32_t* a, const uint32_t* b) {
    asm volatile("mma.sync.aligned.m16n8k8.row.col.f32.tf32.tf32.f32 "
        "{%0,%1,%2,%3}, {%4,%5,%6,%7}, {%8,%9}, {%0,%1,%2,%3};"
        : "+f"(c[0]), "+f"(c[1]), "+f"(c[2]), "+f"(c[3])
        : "r"(a[0]), "r"(a[1]), "r"(a[2]), "r"(a[3]), "r"(b[0]), "r"(b[1]));
}

__device__ __forceinline__ void lda_frag(uint32_t* a, const float* s, int lds,
                                         int mbase, int k, int lane) {
    const float* p = s + (size_t)(mbase + (lane >> 2)) * lds + k + (lane & 3);
    a[0] = __float_as_uint(p[0]);
    a[1] = __float_as_uint(p[8 * lds]);
    a[2] = __float_as_uint(p[4]);
    a[3] = __float_as_uint(p[8 * lds + 4]);
}
__device__ __forceinline__ void ldb_frag(uint32_t* b, const float* s, int lds,
                                         int nbase, int k, int lane) {
    const float* p = s + (size_t)(nbase + (lane >> 2)) * lds + k + (lane & 3);
    b[0] = __float_as_uint(p[0]);
    b[1] = __float_as_uint(p[4]);
}

__device__ __forceinline__ uint32_t smaddr(const void* p) {
    return (uint32_t)__cvta_generic_to_shared(p);
}
#define CP_ASYNC16(dst, src) \
    asm volatile("cp.async.cg.shared.global [%0], [%1], 16;" :: "r"(dst), "l"(src))
#define CP_COMMIT() asm volatile("cp.async.commit_group;" ::: "memory")
#define CP_WAIT0()  asm volatile("cp.async.wait_group 0;" ::: "memory")
#define CP_WAIT1()  asm volatile("cp.async.wait_group 1;" ::: "memory")

// ---------------------------------------------------------------------------
// Fused weight pre-round: g_rW[y] = tf32(W_y), y in {0..3}.
// ---------------------------------------------------------------------------
__global__ __launch_bounds__(256) void round_w(const float* __restrict__ Wq,
                                               const float* __restrict__ Wk,
                                               const float* __restrict__ Wv,
                                               const float* __restrict__ Wo,
                                               float* __restrict__ out) {
    const int which = blockIdx.y;
    const float* src = (which == 0) ? Wq : (which == 1) ? Wk : (which == 2) ? Wv : Wo;
    float* dst = out + (size_t)which * H_ * H_;
    int i = blockIdx.x * 256 + threadIdx.x;   // n4 = H*H/4
    float4 v = ((const float4*)src)[i];
    v.x = tf32f(v.x); v.y = tf32f(v.y); v.z = tf32f(v.z); v.w = tf32f(v.w);
    ((float4*)dst)[i] = v;
}

// ---------------------------------------------------------------------------
// Projection GEMM: C[m,n] = A[m,:]·W[n,:] + bias[n]. Tile 128x128.
// A: raw fp32, register-prefetched, tf32-rounded at STS (once per element).
// W: PRE-ROUNDED, 2-stage cp.async. Mainloop has zero cvt.
// NOTE: post-MMA __syncthreads is REQUIRED — it orders iteration it's MMA
// reads of sA[s]/sB[s] before iteration it+1's cp.async/STS overwrites.
// mode 0: out[m][n] fp32; mode 1: out[b,h,s,d] tf32; mode 2: tf32 * 1/8 (Q)
// ---------------------------------------------------------------------------
__global__ __launch_bounds__(256, 2) void proj_mma(const float* __restrict__ A,
                                                   const float* __restrict__ W,
                                                   const float* __restrict__ bias,
                                                   float* __restrict__ out, int mode) {
    __shared__ float sA[2][128][36];
    __shared__ float sB[2][128][36];
    const int tid = threadIdx.x, lane = tid & 31, w = tid >> 5;
    const int wm = (w >> 2) * 64, wn = (w & 3) * 32;
    const int m0 = blockIdx.y * 128, n0 = blockIdx.x * 128;

    float acc[4][4][4] = {};
    float4 aReg[4];

    // Per-thread staging coordinates (1024 float4 per chunk / 256 threads = 4)
    int rr[4], cc[4];
    #pragma unroll
    for (int i = 0; i < 4; i++) {
        int idx = tid + i * 256;
        rr[i] = idx >> 3;
        cc[i] = (idx & 7) * 4;
    }

    // Prefetch A chunk 0 into registers; W chunk 0 via cp.async.
    #pragma unroll
    for (int i = 0; i < 4; i++)
        aReg[i] = *(const float4*)&A[(size_t)(m0 + rr[i]) * H_ + cc[i]];
    #pragma unroll
    for (int i = 0; i < 4; i++)
        CP_ASYNC16(smaddr(&sB[0][rr[i]][cc[i]]), &W[(size_t)(n0 + rr[i]) * H_ + cc[i]]);
    CP_COMMIT();

    for (int it = 0; it < 32; it++) {
        const int s = it & 1;

        // cvt + STS A chunk it (from prefetched registers)
        #pragma unroll
        for (int i = 0; i < 4; i++) {
            float4 v = aReg[i];
            v.x = tf32f(v.x); v.y = tf32f(v.y); v.z = tf32f(v.z); v.w = tf32f(v.w);
            *(float4*)&sA[s][rr[i]][cc[i]] = v;
        }

        if (it + 1 < 32) {
            const int kn = (it + 1) * 32, sn = s ^ 1;
            #pragma unroll
            for (int i = 0; i < 4; i++)
                aReg[i] = *(const float4*)&A[(size_t)(m0 + rr[i]) * H_ + kn + cc[i]];
            #pragma unroll
            for (int i = 0; i < 4; i++)
                CP_ASYNC16(smaddr(&sB[sn][rr[i]][cc[i]]), &W[(size_t)(n0 + rr[i]) * H_ + kn + cc[i]]);
            CP_COMMIT();
            CP_WAIT1();
        } else {
            CP_WAIT0();
        }
        __syncthreads();

        #pragma unroll
        for (int ks = 0; ks < 4; ks++) {
            uint32_t af[4][4], bf[4][2];
            #pragma unroll
            for (int mt = 0; mt < 4; mt++) lda_frag(af[mt], &sA[s][0][0], 36, wm + mt * 16, ks * 8, lane);
            #pragma unroll
            for (int nt = 0; nt < 4; nt++) ldb_frag(bf[nt], &sB[s][0][0], 36, wn + nt * 8, ks * 8, lane);
            #pragma unroll
            for (int mt = 0; mt < 4; mt++)
                #pragma unroll
                for (int nt = 0; nt < 4; nt++)
                    mma_tf32(acc[mt][nt], af[mt], bf[nt]);
        }
        __syncthreads();   // REQUIRED: protect sA[s]/sB[s] from next iter's writes
    }

    #pragma unroll
    for (int mt = 0; mt < 4; mt++) {
        #pragma unroll
        for (int nt = 0; nt < 4; nt++) {
            int r0 = m0 + wm + mt * 16 + (lane >> 2);
            int c0 = n0 + wn + nt * 8 + (lane & 3) * 2;
            #pragma unroll
            for (int e = 0; e < 4; e++) {
                int m = r0 + (e >> 1) * 8;
                int n = c0 + (e & 1);
                float v = acc[mt][nt][e] + bias[n];
                if (mode == 0) {
                    out[(size_t)m * H_ + n] = v;
                } else {
                    int b = m >> 11, sq = m & 2047, h = n >> 6, dd = n & 63;
                    float o = tf32f(v);
                    if (mode == 2) o *= SCALE_INV;   // exact (exponent shift)
                    out[(((size_t)(b * NH_ + h) * S_) + sq) * HD_ + dd] = o;
                }
            }
        }
    }
}

// ---------------------------------------------------------------------------
// Energy + exp + mask (R7 version). Tile 128(q) x 64(k). Q pre-scaled by 1/8.
// Mask prefetched + bit-packed in the prologue. Writes tf32 unnormalized P.
// ---------------------------------------------------------------------------
__global__ __launch_bounds__(256, 3) void energy_exp(const int* __restrict__ mask,
                                                     float* __restrict__ attn,
                                                     float* __restrict__ psum) {
    __shared__ union {
        struct { float A[128][68]; float B[64][68]; } ld;
        float E[128][68];
    } sm;
    const int tid = threadIdx.x, lane = tid & 31, w = tid >> 5;
    const int wm = (w >> 1) * 32, wn = (w & 1) * 32;
    const int bh = blockIdx.z, b = bh >> 4;
    const int q0 = blockIdx.y * 128, k0 = blockIdx.x * 64;
    const int kblk = blockIdx.x;
    const float* Qb = g_Q + (size_t)bh * S_ * HD_;
    const float* Kb = g_K + (size_t)bh * S_ * HD_;

    #pragma unroll
    for (int i = tid; i < 2048; i += 256) {
        int r = i >> 4, c4 = (i & 15) * 4;
        CP_ASYNC16(smaddr(&sm.ld.A[r][c4]), &Qb[(size_t)(q0 + r) * HD_ + c4]);
    }
    #pragma unroll
    for (int i = tid; i < 1024; i += 256) {
        int r = i >> 4, c4 = (i & 15) * 4;
        CP_ASYNC16(smaddr(&sm.ld.B[r][c4]), &Kb[(size_t)(k0 + r) * HD_ + c4]);
    }
    CP_COMMIT();

    // Mask prefetch + bit-pack (latency hidden under tile load + MMA).
    const int* mb = mask + (size_t)b * S_ * S_;
    const int cl = (tid & 15) * 4;
    const int k = k0 + cl;
    uint32_t pmask = 0;
    #pragma unroll
    for (int j = 0; j < 8; j++) {
        int q = q0 + j * 16 + (tid >> 4);
        int4 mv = *(const int4*)&mb[(size_t)q * S_ + k];
        uint32_t bits = (mv.x ? 1u : 0u) | (mv.y ? 2u : 0u)
                      | (mv.z ? 4u : 0u) | (mv.w ? 8u : 0u);
        pmask |= bits << (4 * j);
    }

    CP_WAIT0();
    __syncthreads();

    float acc[2][4][4] = {};
    #pragma unroll
    for (int ks = 0; ks < 8; ks++) {
        uint32_t af[2][4], bf[4][2];
        #pragma unroll
        for (int mt = 0; mt < 2; mt++) lda_frag(af[mt], &sm.ld.A[0][0], 68, wm + mt * 16, ks * 8, lane);
        #pragma unroll
        for (int nt = 0; nt < 4; nt++) ldb_frag(bf[nt], &sm.ld.B[0][0], 68, wn + nt * 8, ks * 8, lane);
        #pragma unroll
        for (int mt = 0; mt < 2; mt++)
            #pragma unroll
            for (int nt = 0; nt < 4; nt++)
                mma_tf32(acc[mt][nt], af[mt], bf[nt]);
    }
    __syncthreads();   // all warps done reading Q/K before E overwrites

    #pragma unroll
    for (int mt = 0; mt < 2; mt++) {
        int r = wm + mt * 16 + (lane >> 2);
        #pragma unroll
        for (int nt = 0; nt < 4; nt++) {
            int lc = wn + nt * 8 + (lane & 3) * 2;
            sm.E[r][lc]         = acc[mt][nt][0];
            sm.E[r][lc + 1]     = acc[mt][nt][1];
            sm.E[r + 8][lc]     = acc[mt][nt][2];
            sm.E[r + 8][lc + 1] = acc[mt][nt][3];
        }
    }
    __syncthreads();

    float* ab = attn + (size_t)bh * S_ * S_;
    #pragma unroll
    for (int j = 0; j < 8; j++) {
        int row = j * 16 + (tid >> 4);
        int q = q0 + row;
        float4 ev = *(float4*)&sm.E[row][cl];
        uint32_t bits = (pmask >> (4 * j)) & 0xfu;
        float p0 = (bits & 1u) ? tf32f(__expf(ev.x)) : 0.f;
        float p1 = (bits & 2u) ? tf32f(__expf(ev.y)) : 0.f;
        float p2 = (bits & 4u) ? tf32f(__expf(ev.z)) : 0.f;
        float p3 = (bits & 8u) ? tf32f(__expf(ev.w)) : 0.f;
        float4 pv4 = { p0, p1, p2, p3 };
        *(float4*)&ab[(size_t)q * S_ + k] = pv4;
        float v = (p0 + p1) + (p2 + p3);
        v += __shfl_xor_sync(0xffffffffu, v, 1);
        v += __shfl_xor_sync(0xffffffffu, v, 2);
        v += __shfl_xor_sync(0xffffffffu, v, 4);
        v += __shfl_xor_sync(0xffffffffu, v, 8);
        if ((tid & 15) == 0)
            psum[((size_t)bh * S_ + q) * 32 + kblk] = v;
    }
}

// ---------------------------------------------------------------------------
// PV + normalize. Tile 128(q) x 64(d), K chunked by 32, 2-stage cp.async.
// MMA on unnormalized tf32 P; normalization at stores. X stored tf32-rounded.
// ---------------------------------------------------------------------------
__global__ __launch_bounds__(256, 3) void pv_norm(float* __restrict__ attn,
                                                  const float* __restrict__ psum) {
    __shared__ float sP[2][128][36];
    __shared__ float sV[2][32][68];
    __shared__ float sInv[128];
    const int tid = threadIdx.x, lane = tid & 31, w = tid >> 5;
    const int wm = (w >> 1) * 32, wn = (w & 1) * 32;
    const int bh = blockIdx.y, b = bh >> 4, h = bh & 15;
    const int q0 = blockIdx.x * 128;
    float* Pb = attn + (size_t)bh * S_ * S_;
    const float* Vb = g_V + (size_t)bh * S_ * HD_;

    if (tid < 128) {
        const float* ps = psum + ((size_t)bh * S_ + q0 + tid) * 32;
        float sum = 0.f;
        #pragma unroll
        for (int i = 0; i < 32; i++) sum += ps[i];
        sInv[tid] = 1.0f / sum;
    }

    #pragma unroll
    for (int i = tid; i < 1024; i += 256) {
        int r = i >> 3, c4 = (i & 7) * 4;
        CP_ASYNC16(smaddr(&sP[0][r][c4]), &Pb[(size_t)(q0 + r) * S_ + c4]);
    }
    #pragma unroll
    for (int i = tid; i < 512; i += 256) {
        int r = i >> 4, c4 = (i & 15) * 4;
        CP_ASYNC16(smaddr(&sV[0][r][c4]), &Vb[(size_t)r * HD_ + c4]);
    }
    CP_COMMIT();

    float acc[2][4][4] = {};

    for (int it = 0; it < 64; it++) {
        const int kc = it * 32, s = it & 1;
        if (it + 1 < 64) {
            const int kn = kc + 32, sn = s ^ 1;
            #pragma unroll
            for (int i = tid; i < 1024; i += 256) {
                int r = i >> 3, c4 = (i & 7) * 4;
                CP_ASYNC16(smaddr(&sP[sn][r][c4]), &Pb[(size_t)(q0 + r) * S_ + kn + c4]);
            }
            #pragma unroll
            for (int i = tid; i < 512; i += 256) {
                int r = i >> 4, c4 = (i & 15) * 4;
                CP_ASYNC16(smaddr(&sV[sn][r][c4]), &Vb[(size_t)(kn + r) * HD_ + c4]);
            }
            CP_COMMIT();
            CP_WAIT1();
        } else {
            CP_WAIT0();
        }
        __syncthreads();

        #pragma unroll
        for (int ks = 0; ks < 4; ks++) {
            uint32_t af[2][4], bf[4][2];
            #pragma unroll
            for (int mt = 0; mt < 2; mt++) lda_frag(af[mt], &sP[s][0][0], 36, wm + mt * 16, ks * 8, lane);
            #pragma unroll
            for (int nt = 0; nt < 4; nt++) {
                const float* p = &sV[s][ks * 8 + (lane & 3)][wn + nt * 8 + (lane >> 2)];
                bf[nt][0] = __float_as_uint(p[0]);
                bf[nt][1] = __float_as_uint(p[4 * 68]);
            }
            #pragma unroll
            for (int mt = 0; mt < 2; mt++)
                #pragma unroll
                for (int nt = 0; nt < 4; nt++)
                    mma_tf32(acc[mt][nt], af[mt], bf[nt]);
        }

        #pragma unroll
        for (int i = tid; i < 1024; i += 256) {
            int r = i >> 3, c4 = (i & 7) * 4;
            float inv = sInv[r];
            float4 v = *(float4*)&sP[s][r][c4];
            v.x *= inv; v.y *= inv; v.z *= inv; v.w *= inv;
            *(float4*)&Pb[(size_t)(q0 + r) * S_ + kc + c4] = v;
        }
        __syncthreads();
    }

    #pragma unroll
    for (int mt = 0; mt < 2; mt++) {
        #pragma unroll
        for (int nt = 0; nt < 4; nt++) {
            int rr = wm + mt * 16 + (lane >> 2);
            int c0 = wn + nt * 8 + (lane & 3) * 2;
            #pragma unroll
            for (int e = 0; e < 4; e++) {
                int rl = rr + (e >> 1) * 8;
                int q = q0 + rl;
                int d = c0 + (e & 1);
                g_X[((size_t)(b * S_ + q)) * H_ + h * HD_ + d] = tf32f(acc[mt][nt][e] * sInv[rl]);
            }
        }
    }
}

// ---------------------------------------------------------------------------
extern "C" void kernel_launch(void* const* d_in, const int* in_sizes, int n_in,
                              void* d_out, int out_size) {
    const float* query = (const float*)d_in[0];
    const float* key   = (const float*)d_in[1];
    const float* value = (const float*)d_in[2];
    const int*   mask  = (const int*)d_in[3];
    const float* Wq = (const float*)d_in[4];  const float* bq = (const float*)d_in[5];
    const float* Wk = (const float*)d_in[6];  const float* bk = (const float*)d_in[7];
    const float* Wv = (const float*)d_in[8];  const float* bv = (const float*)d_in[9];
    const float* Wo = (const float*)d_in[10]; const float* bo = (const float*)d_in[11];

    float* out  = (float*)d_out;
    float* attn = out + (size_t)B_ * S_ * H_;

    float *gQ, *gK, *gV, *gX, *gPS, *gW;
    cudaGetSymbolAddress((void**)&gQ, g_Q);
    cudaGetSymbolAddress((void**)&gK, g_K);
    cudaGetSymbolAddress((void**)&gV, g_V);
    cudaGetSymbolAddress((void**)&gX, g_X);
    cudaGetSymbolAddress((void**)&gPS, g_psum);
    cudaGetSymbolAddress((void**)&gW, g_rW);

    float* rWq = gW;
    float* rWk = gW + (size_t)H_ * H_;
    float* rWv = gW + (size_t)2 * H_ * H_;
    float* rWo = gW + (size_t)3 * H_ * H_;

    dim3 grid_rw(H_ * H_ / 4 / 256, 4);        // (1024, 4)
    round_w<<<grid_rw, 256>>>(Wq, Wk, Wv, Wo, gW);

    dim3 grid_proj(H_ / 128, M_ / 128);        // (8, 64)
    proj_mma<<<grid_proj, 256>>>(query, rWq, bq, gQ, 2);   // Q pre-scaled 1/8
    proj_mma<<<grid_proj, 256>>>(key,   rWk, bk, gK, 1);
    proj_mma<<<grid_proj, 256>>>(value, rWv, bv, gV, 1);

    dim3 grid_e(S_ / 64, S_ / 128, B_ * NH_);  // (32, 16, 64)
    energy_exp<<<grid_e, 256>>>(mask, attn, gPS);

    dim3 grid_pv(S_ / 128, B_ * NH_);          // (16, 64)
    pv_norm<<<grid_pv, 256>>>(attn, gPS);

    proj_mma<<<grid_proj, 256>>>(gX, rWo, bo, out, 0);
}